// round 1
// baseline (speedup 1.0000x reference)
#include <cuda_runtime.h>

// Problem constants (fixed shapes for this problem)
#define L_LAYERS 20
#define M_IN     80
#define C        64      // R = D = S = 64
#define TILE     128     // time columns per CTA
#define NTH      256
#define WPAD     68      // padded row stride (floats) for transposed weights:
                         // 68*4 = 272 bytes -> 16B-aligned float4 rows, conflict-managed STS

// Shared memory layout (floats):
//   w0 : [80][WPAD]  = 5440   (transposed weight, k-major; large enough for causal K=80)
//   w1 : [64][WPAD]  = 4352
//   w2 : [64][WPAD]  = 4352
//   h  : [64][TILE]  = 8192
//   f  : [64][TILE]  = 8192
//   x  : [80][TILE]  = 10240
// total = 40768 floats = 163072 bytes
#define SMEM_FLOATS 40768

__device__ __forceinline__ float fast_tanh(float x) {
    // tanh(x) = 1 - 2/(exp(2x)+1); abs error ~1e-6 (EX2/RCP approx), handles +/-inf.
    float e = __expf(2.0f * x);
    return 1.0f - __fdividef(2.0f, e + 1.0f);
}

__global__ __launch_bounds__(NTH, 1)
void wavenet_kernel(const float* __restrict__ x,
                    const float* __restrict__ w_causal,  // [64][80]
                    const float* __restrict__ b_causal,  // [64]
                    const float* __restrict__ w_dil,     // [L][64][64]
                    const float* __restrict__ b_dil,     // [L][64]
                    const float* __restrict__ w_res,     // [L][64][64]
                    const float* __restrict__ b_res,     // [L][64]
                    const float* __restrict__ w_skip,    // [L][64][64]
                    const float* __restrict__ b_skip,    // [L][64]
                    const float* __restrict__ w_post1,   // [64][64]
                    const float* __restrict__ b_post1,   // [64]
                    const float* __restrict__ w_post2,   // [1][64]
                    const float* __restrict__ b_post2,   // [1]
                    float* __restrict__ out,             // [B][T]
                    int T)
{
    extern __shared__ float smem[];
    float* w0  = smem;                    // 80*WPAD
    float* w1  = w0 + 80 * WPAD;          // 64*WPAD
    float* w2  = w1 + 64 * WPAD;          // 64*WPAD
    float* hsh = w2 + 64 * WPAD;          // 64*TILE
    float* fsh = hsh + 64 * TILE;         // 64*TILE
    float* xsh = fsh + 64 * TILE;         // 80*TILE

    const int tx  = threadIdx.x;
    const int cg  = tx >> 4;              // 0..15 -> 4 output channels each
    const int lg  = tx & 15;              // 0..15 -> column groups
    const int ch0 = cg * 4;
    const int c0a = lg * 4;               // cols {c0a..c0a+3}
    const int c0b = 64 + lg * 4;          // cols {c0b..c0b+3}

    const int b   = blockIdx.y;
    const long t0 = (long)blockIdx.x * TILE;

    // ---- stage x tile (coalesced) ----
    const float* xg = x + (size_t)b * M_IN * (size_t)T + t0;
    #pragma unroll 4
    for (int i = tx; i < M_IN * TILE; i += NTH) {
        int m = i >> 7, col = i & 127;
        xsh[m * TILE + col] = xg[(size_t)m * T + col];
    }
    // ---- stage w_causal transposed: w0[k*WPAD + r] = wc[r][k] ----
    for (int i = tx; i < C * M_IN; i += NTH) {
        int r = i / M_IN, k = i - r * M_IN;
        w0[k * WPAD + r] = w_causal[i];
    }
    __syncthreads();

    float acc[4][8];

    // ---- h = Wc @ x + bc ----
    {
        #pragma unroll
        for (int i = 0; i < 4; ++i) {
            float bc = b_causal[ch0 + i];
            #pragma unroll
            for (int j = 0; j < 8; ++j) acc[i][j] = bc;
        }
        #pragma unroll 8
        for (int k = 0; k < M_IN; ++k) {
            float4 w4 = *(const float4*)(w0 + k * WPAD + ch0);
            float4 a4 = *(const float4*)(xsh + k * TILE + c0a);
            float4 b4 = *(const float4*)(xsh + k * TILE + c0b);
            float wv[4] = {w4.x, w4.y, w4.z, w4.w};
            float av[8] = {a4.x, a4.y, a4.z, a4.w, b4.x, b4.y, b4.z, b4.w};
            #pragma unroll
            for (int i = 0; i < 4; ++i)
                #pragma unroll
                for (int j = 0; j < 8; ++j)
                    acc[i][j] = fmaf(wv[i], av[j], acc[i][j]);
        }
        #pragma unroll
        for (int i = 0; i < 4; ++i) {
            *(float4*)(hsh + (ch0 + i) * TILE + c0a) =
                make_float4(acc[i][0], acc[i][1], acc[i][2], acc[i][3]);
            *(float4*)(hsh + (ch0 + i) * TILE + c0b) =
                make_float4(acc[i][4], acc[i][5], acc[i][6], acc[i][7]);
        }
    }

    float skip[4][8];
    #pragma unroll
    for (int i = 0; i < 4; ++i)
        #pragma unroll
        for (int j = 0; j < 8; ++j) skip[i][j] = 0.0f;

    // ---- layer loop ----
    for (int l = 0; l < L_LAYERS; ++l) {
        __syncthreads();  // prior reads of w*, writes of hsh complete
        const float* wd = w_dil  + l * 4096;
        const float* ws = w_skip + l * 4096;
        const float* wr = w_res  + l * 4096;
        for (int i = tx; i < 4096; i += NTH) {
            int o = i >> 6, k = i & 63;
            w0[k * WPAD + o] = wd[i];
            w1[k * WPAD + o] = ws[i];
            w2[k * WPAD + o] = wr[i];
        }
        __syncthreads();

        // f = tanh(Wd @ h + bd)
        #pragma unroll
        for (int i = 0; i < 4; ++i) {
            float bd = b_dil[l * C + ch0 + i];
            #pragma unroll
            for (int j = 0; j < 8; ++j) acc[i][j] = bd;
        }
        #pragma unroll 8
        for (int k = 0; k < C; ++k) {
            float4 w4 = *(const float4*)(w0 + k * WPAD + ch0);
            float4 a4 = *(const float4*)(hsh + k * TILE + c0a);
            float4 b4 = *(const float4*)(hsh + k * TILE + c0b);
            float wv[4] = {w4.x, w4.y, w4.z, w4.w};
            float av[8] = {a4.x, a4.y, a4.z, a4.w, b4.x, b4.y, b4.z, b4.w};
            #pragma unroll
            for (int i = 0; i < 4; ++i)
                #pragma unroll
                for (int j = 0; j < 8; ++j)
                    acc[i][j] = fmaf(wv[i], av[j], acc[i][j]);
        }
        #pragma unroll
        for (int i = 0; i < 4; ++i) {
            float4 fa = make_float4(fast_tanh(acc[i][0]), fast_tanh(acc[i][1]),
                                    fast_tanh(acc[i][2]), fast_tanh(acc[i][3]));
            float4 fb = make_float4(fast_tanh(acc[i][4]), fast_tanh(acc[i][5]),
                                    fast_tanh(acc[i][6]), fast_tanh(acc[i][7]));
            *(float4*)(fsh + (ch0 + i) * TILE + c0a) = fa;
            *(float4*)(fsh + (ch0 + i) * TILE + c0b) = fb;
        }
        __syncthreads();

        // skip += Ws @ f + bs ;  h += Wr @ f + br   (fused k-loop)
        float hupd[4][8];
        #pragma unroll
        for (int i = 0; i < 4; ++i) {
            float br_ = b_res[l * C + ch0 + i];
            float bs_ = b_skip[l * C + ch0 + i];
            #pragma unroll
            for (int j = 0; j < 8; ++j) { hupd[i][j] = br_; skip[i][j] += bs_; }
        }
        #pragma unroll 8
        for (int k = 0; k < C; ++k) {
            float4 s4 = *(const float4*)(w1 + k * WPAD + ch0);
            float4 r4 = *(const float4*)(w2 + k * WPAD + ch0);
            float4 a4 = *(const float4*)(fsh + k * TILE + c0a);
            float4 b4 = *(const float4*)(fsh + k * TILE + c0b);
            float sv[4] = {s4.x, s4.y, s4.z, s4.w};
            float rv[4] = {r4.x, r4.y, r4.z, r4.w};
            float av[8] = {a4.x, a4.y, a4.z, a4.w, b4.x, b4.y, b4.z, b4.w};
            #pragma unroll
            for (int i = 0; i < 4; ++i)
                #pragma unroll
                for (int j = 0; j < 8; ++j) {
                    skip[i][j] = fmaf(sv[i], av[j], skip[i][j]);
                    hupd[i][j] = fmaf(rv[i], av[j], hupd[i][j]);
                }
        }
        // h tile update (thread-exclusive tile; no race)
        #pragma unroll
        for (int i = 0; i < 4; ++i) {
            float4 ha = *(const float4*)(hsh + (ch0 + i) * TILE + c0a);
            float4 hb = *(const float4*)(hsh + (ch0 + i) * TILE + c0b);
            ha.x += hupd[i][0]; ha.y += hupd[i][1]; ha.z += hupd[i][2]; ha.w += hupd[i][3];
            hb.x += hupd[i][4]; hb.y += hupd[i][5]; hb.z += hupd[i][6]; hb.w += hupd[i][7];
            *(float4*)(hsh + (ch0 + i) * TILE + c0a) = ha;
            *(float4*)(hsh + (ch0 + i) * TILE + c0b) = hb;
        }
    }

    // ---- post-network ----
    __syncthreads();  // last layer's reads of w1/w2/fsh complete
    for (int i = tx; i < 4096; i += NTH) {
        int o = i >> 6, k = i & 63;
        w0[k * WPAD + o] = w_post1[i];
    }
    if (tx < C) w1[tx] = w_post2[tx];
    // s = tanh(skip) -> fsh (own tile)
    #pragma unroll
    for (int i = 0; i < 4; ++i) {
        float4 fa = make_float4(fast_tanh(skip[i][0]), fast_tanh(skip[i][1]),
                                fast_tanh(skip[i][2]), fast_tanh(skip[i][3]));
        float4 fb = make_float4(fast_tanh(skip[i][4]), fast_tanh(skip[i][5]),
                                fast_tanh(skip[i][6]), fast_tanh(skip[i][7]));
        *(float4*)(fsh + (ch0 + i) * TILE + c0a) = fa;
        *(float4*)(fsh + (ch0 + i) * TILE + c0b) = fb;
    }
    __syncthreads();

    // s2 = tanh(W1 @ s + b1) -> hsh (own tile)
    #pragma unroll
    for (int i = 0; i < 4; ++i) {
        float bp = b_post1[ch0 + i];
        #pragma unroll
        for (int j = 0; j < 8; ++j) acc[i][j] = bp;
    }
    #pragma unroll 8
    for (int k = 0; k < C; ++k) {
        float4 w4 = *(const float4*)(w0 + k * WPAD + ch0);
        float4 a4 = *(const float4*)(fsh + k * TILE + c0a);
        float4 b4 = *(const float4*)(fsh + k * TILE + c0b);
        float wv[4] = {w4.x, w4.y, w4.z, w4.w};
        float av[8] = {a4.x, a4.y, a4.z, a4.w, b4.x, b4.y, b4.z, b4.w};
        #pragma unroll
        for (int i = 0; i < 4; ++i)
            #pragma unroll
            for (int j = 0; j < 8; ++j)
                acc[i][j] = fmaf(wv[i], av[j], acc[i][j]);
    }
    #pragma unroll
    for (int i = 0; i < 4; ++i) {
        float4 fa = make_float4(fast_tanh(acc[i][0]), fast_tanh(acc[i][1]),
                                fast_tanh(acc[i][2]), fast_tanh(acc[i][3]));
        float4 fb = make_float4(fast_tanh(acc[i][4]), fast_tanh(acc[i][5]),
                                fast_tanh(acc[i][6]), fast_tanh(acc[i][7]));
        *(float4*)(hsh + (ch0 + i) * TILE + c0a) = fa;
        *(float4*)(hsh + (ch0 + i) * TILE + c0b) = fb;
    }
    __syncthreads();

    // out[b][t0+col] = b2 + sum_s w2[s] * s2[s][col]
    if (tx < TILE) {
        float o = b_post2[0];
        #pragma unroll 16
        for (int s = 0; s < C; ++s)
            o = fmaf(w1[s], hsh[s * TILE + tx], o);
        out[(size_t)b * T + t0 + tx] = o;
    }
}

extern "C" void kernel_launch(void* const* d_in, const int* in_sizes, int n_in,
                              void* d_out, int out_size)
{
    const float* x        = (const float*)d_in[0];
    const float* w_causal = (const float*)d_in[1];
    const float* b_causal = (const float*)d_in[2];
    const float* w_dil    = (const float*)d_in[3];
    const float* b_dil    = (const float*)d_in[4];
    const float* w_res    = (const float*)d_in[5];
    const float* b_res    = (const float*)d_in[6];
    const float* w_skip   = (const float*)d_in[7];
    const float* b_skip   = (const float*)d_in[8];
    const float* w_post1  = (const float*)d_in[9];
    const float* b_post1  = (const float*)d_in[10];
    const float* w_post2  = (const float*)d_in[11];
    const float* b_post2  = (const float*)d_in[12];
    float* out = (float*)d_out;

    const int B = 4;
    const int T = out_size / B;           // 65536

    const size_t smem_bytes = SMEM_FLOATS * sizeof(float);  // 163072
    cudaFuncSetAttribute(wavenet_kernel,
                         cudaFuncAttributeMaxDynamicSharedMemorySize,
                         (int)smem_bytes);

    dim3 grid(T / TILE, B);
    wavenet_kernel<<<grid, NTH, smem_bytes>>>(
        x, w_causal, b_causal, w_dil, b_dil, w_res, b_res,
        w_skip, b_skip, w_post1, b_post1, w_post2, b_post2, out, T);
}

// round 2
// speedup vs baseline: 1.0848x; 1.0848x over previous
#include <cuda_runtime.h>

// Fixed shapes
#define L_LAYERS 20
#define M_IN     80
#define C        64
#define TILE     256    // time columns per CTA
#define NTH      256

// smem (floats): w0 5120 | w1 4096 | w2 4096 | h 64*256 | f 64*256  = 46080 fl = 184320 B
#define SMEM_FLOATS 46080

typedef unsigned long long u64;

__device__ __forceinline__ u64 ffma2(u64 a, u64 b, u64 c) {
    u64 d; asm("fma.rn.f32x2 %0,%1,%2,%3;" : "=l"(d) : "l"(a), "l"(b), "l"(c)); return d;
}
__device__ __forceinline__ u64 fadd2(u64 a, u64 b) {
    u64 d; asm("add.rn.f32x2 %0,%1,%2;" : "=l"(d) : "l"(a), "l"(b)); return d;
}
__device__ __forceinline__ u64 dup2(float x) {
    u64 d; asm("mov.b64 %0,{%1,%1};" : "=l"(d) : "f"(x)); return d;
}
__device__ __forceinline__ float2 unpk(u64 v) {
    float lo, hi; asm("mov.b64 {%0,%1},%2;" : "=f"(lo), "=f"(hi) : "l"(v));
    return make_float2(lo, hi);
}
__device__ __forceinline__ float fast_tanh(float x) {
    // tanh(x) = 1 - 2/(exp(2x)+1); ~1e-6 abs err, inf-safe
    float e = __expf(2.0f * x);
    return 1.0f - __fdividef(2.0f, e + 1.0f);
}

__global__ __launch_bounds__(NTH, 1)
void wavenet_kernel(const float* __restrict__ x,
                    const float* __restrict__ w_causal,  // [64][80]
                    const float* __restrict__ b_causal,  // [64]
                    const float* __restrict__ w_dil,     // [L][64][64]
                    const float* __restrict__ b_dil,     // [L][64]
                    const float* __restrict__ w_res,     // [L][64][64]
                    const float* __restrict__ b_res,     // [L][64]
                    const float* __restrict__ w_skip,    // [L][64][64]
                    const float* __restrict__ b_skip,    // [L][64]
                    const float* __restrict__ w_post1,   // [64][64]
                    const float* __restrict__ b_post1,   // [64]
                    const float* __restrict__ w_post2,   // [1][64]
                    const float* __restrict__ b_post2,   // [1]
                    float* __restrict__ out,             // [B][T]
                    int T)
{
    extern __shared__ float smem[];
    float* w0s = smem;                 // 5120 (causal [64][80] or dil [64][64])
    float* w1s = w0s + 5120;           // 4096 (skip / post2)
    float* w2s = w1s + 4096;           // 4096 (res)
    float* hsh = w2s + 4096;           // [64][TILE]
    float* fsh = hsh + 64 * TILE;      // [64][TILE]  (also x staging buffer)

    const int tx  = threadIdx.x;
    const int cg  = tx >> 5;           // 8 channel groups of 8 channels
    const int lg  = tx & 31;           // 32 column groups
    const int ch0 = cg * 8;
    const int c0a = lg * 4;            // cols {c0a..c0a+3}
    const int c0b = 128 + lg * 4;      // cols {c0b..c0b+3}

    const int b   = blockIdx.y;
    const long t0 = (long)blockIdx.x * TILE;

    // ---- stage causal weights (direct copy, [64][80]) ----
    {
        const float4* wc4 = (const float4*)w_causal;     // 80%4==0, rows aligned
        float4* w04 = (float4*)w0s;
        #pragma unroll
        for (int i = tx; i < (C * M_IN) / 4; i += NTH) w04[i] = wc4[i];
    }

    // ---- causal conv: h = Wc @ x + bc, K=80 in two 40-row x chunks ----
    u64 acc2[8][4];
    #pragma unroll
    for (int i = 0; i < 8; ++i) {
        u64 bc2 = dup2(b_causal[ch0 + i]);
        #pragma unroll
        for (int jp = 0; jp < 4; ++jp) acc2[i][jp] = bc2;
    }
    const float* xg = x + (size_t)b * M_IN * (size_t)T + t0;
    for (int chunk = 0; chunk < 2; ++chunk) {
        __syncthreads();
        const int kbase = chunk * 40;
        #pragma unroll 5
        for (int idx = tx; idx < 40 * TILE; idx += NTH) {
            int r = idx >> 8, col = idx & 255;
            fsh[r * TILE + col] = xg[(size_t)(kbase + r) * T + col];
        }
        __syncthreads();
        #pragma unroll 4
        for (int kk = 0; kk < 40; ++kk) {
            ulonglong2 a0 = *(const ulonglong2*)(fsh + kk * TILE + c0a);
            ulonglong2 a1 = *(const ulonglong2*)(fsh + kk * TILE + c0b);
            u64 av[4] = {a0.x, a0.y, a1.x, a1.y};
            #pragma unroll
            for (int i = 0; i < 8; ++i) {
                u64 wd2 = dup2(w0s[(ch0 + i) * M_IN + kbase + kk]);
                #pragma unroll
                for (int jp = 0; jp < 4; ++jp)
                    acc2[i][jp] = ffma2(av[jp], wd2, acc2[i][jp]);
            }
        }
    }
    // write h (own tile)
    #pragma unroll
    for (int i = 0; i < 8; ++i) {
        *(ulonglong2*)(hsh + (ch0 + i) * TILE + c0a) = make_ulonglong2(acc2[i][0], acc2[i][1]);
        *(ulonglong2*)(hsh + (ch0 + i) * TILE + c0b) = make_ulonglong2(acc2[i][2], acc2[i][3]);
    }

    u64 skip2[8][4];
    #pragma unroll
    for (int i = 0; i < 8; ++i)
        #pragma unroll
        for (int jp = 0; jp < 4; ++jp) skip2[i][jp] = 0ULL;

    // ================= layer loop =================
    for (int l = 0; l < L_LAYERS; ++l) {
        __syncthreads();   // prev fused reads of w1s/w2s/fsh + h writes complete
        // stage weights (direct [o][k] layout, float4 both sides)
        {
            const float4* wd4 = (const float4*)(w_dil  + l * 4096);
            const float4* ws4 = (const float4*)(w_skip + l * 4096);
            const float4* wr4 = (const float4*)(w_res  + l * 4096);
            float4* p0 = (float4*)w0s; float4* p1 = (float4*)w1s; float4* p2 = (float4*)w2s;
            #pragma unroll
            for (int i = tx; i < 1024; i += NTH) {
                p0[i] = wd4[i]; p1[i] = ws4[i]; p2[i] = wr4[i];
            }
        }
        __syncthreads();

        // ---- f = tanh(Wd @ h + bd) ----
        #pragma unroll
        for (int i = 0; i < 8; ++i) {
            u64 bd2 = dup2(b_dil[l * C + ch0 + i]);
            #pragma unroll
            for (int jp = 0; jp < 4; ++jp) acc2[i][jp] = bd2;
        }
        #pragma unroll 4
        for (int k = 0; k < C; ++k) {
            ulonglong2 a0 = *(const ulonglong2*)(hsh + k * TILE + c0a);
            ulonglong2 a1 = *(const ulonglong2*)(hsh + k * TILE + c0b);
            u64 av[4] = {a0.x, a0.y, a1.x, a1.y};
            #pragma unroll
            for (int i = 0; i < 8; ++i) {
                u64 wd2 = dup2(w0s[(ch0 + i) * C + k]);
                #pragma unroll
                for (int jp = 0; jp < 4; ++jp)
                    acc2[i][jp] = ffma2(av[jp], wd2, acc2[i][jp]);
            }
        }
        #pragma unroll
        for (int i = 0; i < 8; ++i) {
            float2 t0 = unpk(acc2[i][0]), t1 = unpk(acc2[i][1]);
            float2 t2 = unpk(acc2[i][2]), t3 = unpk(acc2[i][3]);
            *(float4*)(fsh + (ch0 + i) * TILE + c0a) =
                make_float4(fast_tanh(t0.x), fast_tanh(t0.y), fast_tanh(t1.x), fast_tanh(t1.y));
            *(float4*)(fsh + (ch0 + i) * TILE + c0b) =
                make_float4(fast_tanh(t2.x), fast_tanh(t2.y), fast_tanh(t3.x), fast_tanh(t3.y));
        }
        __syncthreads();

        // ---- skip += Ws@f + bs ; h = h + Wr@f + br (fused) ----
        u64 hup[8][4];
        #pragma unroll
        for (int i = 0; i < 8; ++i) {
            u64 br2 = dup2(b_res[l * C + ch0 + i]);
            u64 bs2 = dup2(b_skip[l * C + ch0 + i]);
            ulonglong2 h0 = *(const ulonglong2*)(hsh + (ch0 + i) * TILE + c0a);
            ulonglong2 h1 = *(const ulonglong2*)(hsh + (ch0 + i) * TILE + c0b);
            hup[i][0] = fadd2(h0.x, br2); hup[i][1] = fadd2(h0.y, br2);
            hup[i][2] = fadd2(h1.x, br2); hup[i][3] = fadd2(h1.y, br2);
            #pragma unroll
            for (int jp = 0; jp < 4; ++jp) skip2[i][jp] = fadd2(skip2[i][jp], bs2);
        }
        #pragma unroll 4
        for (int k = 0; k < C; ++k) {
            ulonglong2 a0 = *(const ulonglong2*)(fsh + k * TILE + c0a);
            ulonglong2 a1 = *(const ulonglong2*)(fsh + k * TILE + c0b);
            u64 av[4] = {a0.x, a0.y, a1.x, a1.y};
            #pragma unroll
            for (int i = 0; i < 8; ++i) {
                u64 ws2 = dup2(w1s[(ch0 + i) * C + k]);
                u64 wr2 = dup2(w2s[(ch0 + i) * C + k]);
                #pragma unroll
                for (int jp = 0; jp < 4; ++jp) {
                    skip2[i][jp] = ffma2(av[jp], ws2, skip2[i][jp]);
                    hup[i][jp]   = ffma2(av[jp], wr2, hup[i][jp]);
                }
            }
        }
        #pragma unroll
        for (int i = 0; i < 8; ++i) {
            *(ulonglong2*)(hsh + (ch0 + i) * TILE + c0a) = make_ulonglong2(hup[i][0], hup[i][1]);
            *(ulonglong2*)(hsh + (ch0 + i) * TILE + c0b) = make_ulonglong2(hup[i][2], hup[i][3]);
        }
    }

    // ================= post network =================
    __syncthreads();  // last fused reads done
    {
        const float4* wp4 = (const float4*)w_post1;
        float4* p0 = (float4*)w0s;
        #pragma unroll
        for (int i = tx; i < 1024; i += NTH) p0[i] = wp4[i];
        if (tx < C) w1s[tx] = w_post2[tx];
    }
    // s = tanh(skip) -> fsh
    #pragma unroll
    for (int i = 0; i < 8; ++i) {
        float2 t0 = unpk(skip2[i][0]), t1 = unpk(skip2[i][1]);
        float2 t2 = unpk(skip2[i][2]), t3 = unpk(skip2[i][3]);
        *(float4*)(fsh + (ch0 + i) * TILE + c0a) =
            make_float4(fast_tanh(t0.x), fast_tanh(t0.y), fast_tanh(t1.x), fast_tanh(t1.y));
        *(float4*)(fsh + (ch0 + i) * TILE + c0b) =
            make_float4(fast_tanh(t2.x), fast_tanh(t2.y), fast_tanh(t3.x), fast_tanh(t3.y));
    }
    __syncthreads();

    // s2 = tanh(W1 @ s + b1) -> hsh
    #pragma unroll
    for (int i = 0; i < 8; ++i) {
        u64 bp2 = dup2(b_post1[ch0 + i]);
        #pragma unroll
        for (int jp = 0; jp < 4; ++jp) acc2[i][jp] = bp2;
    }
    #pragma unroll 4
    for (int k = 0; k < C; ++k) {
        ulonglong2 a0 = *(const ulonglong2*)(fsh + k * TILE + c0a);
        ulonglong2 a1 = *(const ulonglong2*)(fsh + k * TILE + c0b);
        u64 av[4] = {a0.x, a0.y, a1.x, a1.y};
        #pragma unroll
        for (int i = 0; i < 8; ++i) {
            u64 w2d = dup2(w0s[(ch0 + i) * C + k]);
            #pragma unroll
            for (int jp = 0; jp < 4; ++jp)
                acc2[i][jp] = ffma2(av[jp], w2d, acc2[i][jp]);
        }
    }
    #pragma unroll
    for (int i = 0; i < 8; ++i) {
        float2 t0 = unpk(acc2[i][0]), t1 = unpk(acc2[i][1]);
        float2 t2 = unpk(acc2[i][2]), t3 = unpk(acc2[i][3]);
        *(float4*)(hsh + (ch0 + i) * TILE + c0a) =
            make_float4(fast_tanh(t0.x), fast_tanh(t0.y), fast_tanh(t1.x), fast_tanh(t1.y));
        *(float4*)(hsh + (ch0 + i) * TILE + c0b) =
            make_float4(fast_tanh(t2.x), fast_tanh(t2.y), fast_tanh(t3.x), fast_tanh(t3.y));
    }
    __syncthreads();

    // out = W2 @ s2 + b2  (1 output channel; thread tx -> column tx)
    {
        float o = b_post2[0];
        #pragma unroll 16
        for (int s = 0; s < C; ++s)
            o = fmaf(w1s[s], hsh[s * TILE + tx], o);
        out[(size_t)b * T + t0 + tx] = o;
    }
}

extern "C" void kernel_launch(void* const* d_in, const int* in_sizes, int n_in,
                              void* d_out, int out_size)
{
    const float* x        = (const float*)d_in[0];
    const float* w_causal = (const float*)d_in[1];
    const float* b_causal = (const float*)d_in[2];
    const float* w_dil    = (const float*)d_in[3];
    const float* b_dil    = (const float*)d_in[4];
    const float* w_res    = (const float*)d_in[5];
    const float* b_res    = (const float*)d_in[6];
    const float* w_skip   = (const float*)d_in[7];
    const float* b_skip   = (const float*)d_in[8];
    const float* w_post1  = (const float*)d_in[9];
    const float* b_post1  = (const float*)d_in[10];
    const float* w_post2  = (const float*)d_in[11];
    const float* b_post2  = (const float*)d_in[12];
    float* out = (float*)d_out;

    const int B = 4;
    const int T = out_size / B;   // 65536

    const size_t smem_bytes = SMEM_FLOATS * sizeof(float);  // 184320
    cudaFuncSetAttribute(wavenet_kernel,
                         cudaFuncAttributeMaxDynamicSharedMemorySize,
                         (int)smem_bytes);

    dim3 grid(T / TILE, B);
    wavenet_kernel<<<grid, NTH, smem_bytes>>>(
        x, w_causal, b_causal, w_dil, b_dil, w_res, b_res,
        w_skip, b_skip, w_post1, b_post1, w_post2, b_post2, out, T);
}

// round 4
// speedup vs baseline: 1.7447x; 1.6084x over previous
#include <cuda_runtime.h>
#include <cuda_bf16.h>
#include <cstdint>

#define L_LAYERS 20
#define ACT_LD   144       // activation/weight plane row stride (64ch*2B + 16 pad)
#define WC_LD    176       // causal x / w_causal plane row stride (80ch*2B + 16 pad)

// ---- smem byte offsets ----
#define H_HI   0           // h plane hi  [128][144]
#define H_LO   18432
#define F_HI   36864       // f plane hi (also s in post)
#define F_LO   55296
#define WD_HI  73728       // weight planes [64][144]
#define WD_LO  82944
#define WS_HI  92160
#define WS_LO  101376
#define WR_HI  110592
#define WR_LO  119808
#define OFF_BD   129024    // f32[64]
#define OFF_BR   129280
#define OFF_BTOT 129536
#define OFF_BP1  129792
#define OFF_WP2  130048
#define OFF_B2   130304
#define SMEM_BYTES 130560
// causal-phase aliases (regions reused before layer 0 weights are staged)
#define X_HI   73728       // x plane hi [128][176]
#define X_LO   96256
#define WCA_HI 36864       // w_causal plane hi [64][176]
#define WCA_LO 48128
#define OFF_BC OFF_BD

__device__ __forceinline__ uint32_t smem_u32(const void* p) {
    uint32_t a;
    asm("{ .reg .u64 t; cvta.to.shared.u64 t, %1; cvt.u32.u64 %0, t; }" : "=r"(a) : "l"(p));
    return a;
}
__device__ __forceinline__ void ldsm4(uint32_t addr, uint32_t r[4]) {
    asm volatile("ldmatrix.sync.aligned.m8n8.x4.shared.b16 {%0,%1,%2,%3}, [%4];"
                 : "=r"(r[0]), "=r"(r[1]), "=r"(r[2]), "=r"(r[3]) : "r"(addr));
}
__device__ __forceinline__ void mma16816(float d[4], const uint32_t a[4],
                                         uint32_t b0, uint32_t b1) {
    asm volatile("mma.sync.aligned.m16n8k16.row.col.f32.bf16.bf16.f32 "
                 "{%0,%1,%2,%3},{%4,%5,%6,%7},{%8,%9},{%0,%1,%2,%3};"
                 : "+f"(d[0]), "+f"(d[1]), "+f"(d[2]), "+f"(d[3])
                 : "r"(a[0]), "r"(a[1]), "r"(a[2]), "r"(a[3]), "r"(b0), "r"(b1));
}
__device__ __forceinline__ float fast_tanh(float x) {
    float e = __expf(2.0f * x);
    return 1.0f - __fdividef(2.0f, e + 1.0f);
}
__device__ __forceinline__ void split_pair(float a, float b, uint32_t& hi, uint32_t& lo) {
    __nv_bfloat16 ha = __float2bfloat16_rn(a), hb = __float2bfloat16_rn(b);
    float ra = a - __bfloat162float(ha), rb = b - __bfloat162float(hb);
    __nv_bfloat16 la = __float2bfloat16_rn(ra), lb = __float2bfloat16_rn(rb);
    hi = (uint32_t)__bfloat16_as_ushort(ha) | ((uint32_t)__bfloat16_as_ushort(hb) << 16);
    lo = (uint32_t)__bfloat16_as_ushort(la) | ((uint32_t)__bfloat16_as_ushort(lb) << 16);
}

// 3-pass split-precision matmul accumulate: d += A x B  (A 16x(16*NKC) rows of this warp,
// B 64x(16*NKC)).  Pass 0: Ahi*Bhi, 1: Alo*Bhi, 2: Ahi*Blo.
template<int NKC, int LDB>
__device__ __forceinline__ void mm3(float d[8][4],
                                    uint32_t aH, uint32_t aL,
                                    uint32_t bH, uint32_t bL,
                                    uint32_t aoff, uint32_t boff) {
    #pragma unroll
    for (int p = 0; p < 3; ++p) {
        uint32_t ab = (p == 1 ? aL : aH) + aoff;
        uint32_t bb = (p == 2 ? bL : bH) + boff;
        #pragma unroll
        for (int kc = 0; kc < NKC; ++kc) {
            uint32_t afr[4]; ldsm4(ab + kc * 32, afr);
            #pragma unroll
            for (int np = 0; np < 4; ++np) {
                uint32_t bfr[4]; ldsm4(bb + kc * 32 + np * (16 * LDB), bfr);
                mma16816(d[np * 2],     afr, bfr[0], bfr[1]);
                mma16816(d[np * 2 + 1], afr, bfr[2], bfr[3]);
            }
        }
    }
}
// fused: ds += A x Bs ; dr += A x Br (shared A fragments)
__device__ __forceinline__ void mm3_dual(float ds[8][4], float dr[8][4],
                                         uint32_t aH, uint32_t aL,
                                         uint32_t sH, uint32_t sL,
                                         uint32_t rH, uint32_t rL,
                                         uint32_t aoff, uint32_t boff) {
    #pragma unroll
    for (int p = 0; p < 3; ++p) {
        uint32_t ab = (p == 1 ? aL : aH) + aoff;
        uint32_t sb = (p == 2 ? sL : sH) + boff;
        uint32_t rb = (p == 2 ? rL : rH) + boff;
        #pragma unroll
        for (int kc = 0; kc < 4; ++kc) {
            uint32_t afr[4]; ldsm4(ab + kc * 32, afr);
            #pragma unroll
            for (int np = 0; np < 4; ++np) {
                uint32_t bs[4]; ldsm4(sb + kc * 32 + np * (16 * ACT_LD), bs);
                mma16816(ds[np * 2],     afr, bs[0], bs[1]);
                mma16816(ds[np * 2 + 1], afr, bs[2], bs[3]);
                uint32_t br_[4]; ldsm4(rb + kc * 32 + np * (16 * ACT_LD), br_);
                mma16816(dr[np * 2],     afr, br_[0], br_[1]);
                mma16816(dr[np * 2 + 1], afr, br_[2], br_[3]);
            }
        }
    }
}

// stage a [64][64] f32 weight into bf16 hi/lo planes ([64][ACT_LD])
__device__ __forceinline__ void stage_w(const float* __restrict__ w, char* sm,
                                        int hiOff, int loOff, int tid) {
    const float4* w4 = (const float4*)w;
    #pragma unroll
    for (int i = tid; i < 1024; i += 256) {
        float4 v = w4[i];
        uint32_t h0, l0, h1, l1;
        split_pair(v.x, v.y, h0, l0);
        split_pair(v.z, v.w, h1, l1);
        int off = (i >> 4) * ACT_LD + (i & 15) * 8;
        *(uint2*)(sm + hiOff + off) = make_uint2(h0, h1);
        *(uint2*)(sm + loOff + off) = make_uint2(l0, l1);
    }
}

__global__ __launch_bounds__(256, 1)
void wavenet_mma(const float* __restrict__ x,
                 const float* __restrict__ w_causal, const float* __restrict__ b_causal,
                 const float* __restrict__ w_dil,    const float* __restrict__ b_dil,
                 const float* __restrict__ w_res,    const float* __restrict__ b_res,
                 const float* __restrict__ w_skip,   const float* __restrict__ b_skip,
                 const float* __restrict__ w_post1,  const float* __restrict__ b_post1,
                 const float* __restrict__ w_post2,  const float* __restrict__ b_post2,
                 float* __restrict__ out, int T)
{
    extern __shared__ char sm[];
    const uint32_t sb = smem_u32(sm);
    const int tid  = threadIdx.x;
    const int wid  = tid >> 5;
    const int lane = tid & 31;
    const int m0   = wid * 16;
    const int b    = blockIdx.y;
    const long t0  = (long)blockIdx.x * 128;

    // per-thread ldmatrix offsets
    const uint32_t a_off  = (uint32_t)(m0 + (lane & 15)) * ACT_LD + ((lane >> 4) << 4);
    const uint32_t b_off  = (uint32_t)((lane & 7) + ((lane >> 4) & 1) * 8) * ACT_LD
                          + (((lane >> 3) & 1) << 4);
    const uint32_t a_offc = (uint32_t)(m0 + (lane & 15)) * WC_LD + ((lane >> 4) << 4);
    const uint32_t b_offc = (uint32_t)((lane & 7) + ((lane >> 4) & 1) * 8) * WC_LD
                          + (((lane >> 3) & 1) << 4);
    // D-fragment epilogue mapping
    const int r0 = (lane >> 2);              // + m0 ; second row r0+8
    const int cq = (lane & 3) * 2;           // column pair within ntile

    // ---- stage x planes (transpose) + w_causal planes + bc ----
    const float* xg = x + (size_t)b * 80 * (size_t)T + t0;
    for (int i = tid; i < 80 * 128; i += 256) {
        int ch = i >> 7, t = i & 127;
        float v = xg[(size_t)ch * T + t];
        __nv_bfloat16 hb = __float2bfloat16_rn(v);
        __nv_bfloat16 lb = __float2bfloat16_rn(v - __bfloat162float(hb));
        int off = t * WC_LD + ch * 2;
        *(__nv_bfloat16*)(sm + X_HI + off) = hb;
        *(__nv_bfloat16*)(sm + X_LO + off) = lb;
    }
    for (int i = tid; i < 64 * 80; i += 256) {
        int o = i / 80, k = i - o * 80;
        float v = w_causal[i];
        __nv_bfloat16 hb = __float2bfloat16_rn(v);
        __nv_bfloat16 lb = __float2bfloat16_rn(v - __bfloat162float(hb));
        int off = o * WC_LD + k * 2;
        *(__nv_bfloat16*)(sm + WCA_HI + off) = hb;
        *(__nv_bfloat16*)(sm + WCA_LO + off) = lb;
    }
    if (tid < 64) ((float*)(sm + OFF_BC))[tid] = b_causal[tid];
    __syncthreads();

    // ---- causal: h = Wc @ x + bc  (h stays fp32 in regs) ----
    float h[8][4];
    #pragma unroll
    for (int n = 0; n < 8; ++n)
        #pragma unroll
        for (int j = 0; j < 4; ++j) h[n][j] = 0.0f;
    mm3<5, WC_LD>(h, sb + X_HI, sb + X_LO, sb + WCA_HI, sb + WCA_LO, a_offc, b_offc);
    #pragma unroll
    for (int n = 0; n < 8; ++n) {
        float2 bc = *(const float2*)(sm + OFF_BC + (n * 8 + cq) * 4);
        h[n][0] += bc.x; h[n][1] += bc.y; h[n][2] += bc.x; h[n][3] += bc.y;
    }
    // store h planes
    {
        int soff = (m0 + r0) * ACT_LD;
        #pragma unroll
        for (int n = 0; n < 8; ++n) {
            int o = soff + (n * 8 + cq) * 2;
            uint32_t hi, lo;
            split_pair(h[n][0], h[n][1], hi, lo);
            *(uint32_t*)(sm + H_HI + o) = hi; *(uint32_t*)(sm + H_LO + o) = lo;
            split_pair(h[n][2], h[n][3], hi, lo);
            *(uint32_t*)(sm + H_HI + o + 8 * ACT_LD) = hi;
            *(uint32_t*)(sm + H_LO + o + 8 * ACT_LD) = lo;
        }
    }
    __syncthreads();   // all causal reads of X/WCA regions done

    // stage layer-0 weights + biases
    stage_w(w_dil,  sm, WD_HI, WD_LO, tid);
    stage_w(w_skip, sm, WS_HI, WS_LO, tid);
    stage_w(w_res,  sm, WR_HI, WR_LO, tid);
    if (tid < 64)       ((float*)(sm + OFF_BD))[tid]       = b_dil[tid];
    else if (tid < 128) ((float*)(sm + OFF_BR))[tid - 64]  = b_res[tid - 64];
    __syncthreads();

    float skip[8][4];
    #pragma unroll
    for (int n = 0; n < 8; ++n)
        #pragma unroll
        for (int j = 0; j < 4; ++j) skip[n][j] = 0.0f;

    // ================= layer loop =================
    #pragma unroll 1
    for (int l = 0; l < L_LAYERS; ++l) {
        // ---- f = tanh(Wd @ h + bd) ----
        float d[8][4];
        #pragma unroll
        for (int n = 0; n < 8; ++n)
            #pragma unroll
            for (int j = 0; j < 4; ++j) d[n][j] = 0.0f;
        mm3<4, ACT_LD>(d, sb + H_HI, sb + H_LO, sb + WD_HI, sb + WD_LO, a_off, b_off);
        {
            int soff = (m0 + r0) * ACT_LD;
            #pragma unroll
            for (int n = 0; n < 8; ++n) {
                float2 bd = *(const float2*)(sm + OFF_BD + (n * 8 + cq) * 4);
                float v0 = fast_tanh(d[n][0] + bd.x), v1 = fast_tanh(d[n][1] + bd.y);
                float v2 = fast_tanh(d[n][2] + bd.x), v3 = fast_tanh(d[n][3] + bd.y);
                int o = soff + (n * 8 + cq) * 2;
                uint32_t hi, lo;
                split_pair(v0, v1, hi, lo);
                *(uint32_t*)(sm + F_HI + o) = hi; *(uint32_t*)(sm + F_LO + o) = lo;
                split_pair(v2, v3, hi, lo);
                *(uint32_t*)(sm + F_HI + o + 8 * ACT_LD) = hi;
                *(uint32_t*)(sm + F_LO + o + 8 * ACT_LD) = lo;
            }
        }
        __syncwarp();

        // ---- skip += Ws @ f ; h += Wr @ f + br ----
        #pragma unroll
        for (int n = 0; n < 8; ++n)
            #pragma unroll
            for (int j = 0; j < 4; ++j) d[n][j] = 0.0f;
        mm3_dual(skip, d, sb + F_HI, sb + F_LO,
                 sb + WS_HI, sb + WS_LO, sb + WR_HI, sb + WR_LO, a_off, b_off);
        {
            int soff = (m0 + r0) * ACT_LD;
            #pragma unroll
            for (int n = 0; n < 8; ++n) {
                float2 br2 = *(const float2*)(sm + OFF_BR + (n * 8 + cq) * 4);
                h[n][0] += d[n][0] + br2.x; h[n][1] += d[n][1] + br2.y;
                h[n][2] += d[n][2] + br2.x; h[n][3] += d[n][3] + br2.y;
                int o = soff + (n * 8 + cq) * 2;
                uint32_t hi, lo;
                split_pair(h[n][0], h[n][1], hi, lo);
                *(uint32_t*)(sm + H_HI + o) = hi; *(uint32_t*)(sm + H_LO + o) = lo;
                split_pair(h[n][2], h[n][3], hi, lo);
                *(uint32_t*)(sm + H_HI + o + 8 * ACT_LD) = hi;
                *(uint32_t*)(sm + H_LO + o + 8 * ACT_LD) = lo;
            }
        }
        __syncthreads();   // everyone done reading this layer's weights/biases

        // ---- stage next weights ----
        if (l < L_LAYERS - 1) {
            stage_w(w_dil  + (l + 1) * 4096, sm, WD_HI, WD_LO, tid);
            stage_w(w_skip + (l + 1) * 4096, sm, WS_HI, WS_LO, tid);
            stage_w(w_res  + (l + 1) * 4096, sm, WR_HI, WR_LO, tid);
            if (tid < 64)       ((float*)(sm + OFF_BD))[tid]      = b_dil[(l + 1) * 64 + tid];
            else if (tid < 128) ((float*)(sm + OFF_BR))[tid - 64] = b_res[(l + 1) * 64 + tid - 64];
        } else {
            stage_w(w_post1, sm, WD_HI, WD_LO, tid);
            if (tid < 64) {
                float s = 0.0f;
                #pragma unroll
                for (int ll = 0; ll < L_LAYERS; ++ll) s += b_skip[ll * 64 + tid];
                ((float*)(sm + OFF_BTOT))[tid] = s;
                ((float*)(sm + OFF_BP1))[tid]  = b_post1[tid];
                ((float*)(sm + OFF_WP2))[tid]  = w_post2[tid];
            }
            if (tid == 128) ((float*)(sm + OFF_B2))[0] = b_post2[0];
        }
        __syncthreads();
    }

    // ---- post: s = tanh(skip + btot) -> F planes ----
    {
        int soff = (m0 + r0) * ACT_LD;
        #pragma unroll
        for (int n = 0; n < 8; ++n) {
            float2 bt = *(const float2*)(sm + OFF_BTOT + (n * 8 + cq) * 4);
            float v0 = fast_tanh(skip[n][0] + bt.x), v1 = fast_tanh(skip[n][1] + bt.y);
            float v2 = fast_tanh(skip[n][2] + bt.x), v3 = fast_tanh(skip[n][3] + bt.y);
            int o = soff + (n * 8 + cq) * 2;
            uint32_t hi, lo;
            split_pair(v0, v1, hi, lo);
            *(uint32_t*)(sm + F_HI + o) = hi; *(uint32_t*)(sm + F_LO + o) = lo;
            split_pair(v2, v3, hi, lo);
            *(uint32_t*)(sm + F_HI + o + 8 * ACT_LD) = hi;
            *(uint32_t*)(sm + F_LO + o + 8 * ACT_LD) = lo;
        }
    }
    __syncwarp();

    // ---- s2 = tanh(W1 @ s + bp1); out = b2 + wp2 . s2 ----
    float d[8][4];
    #pragma unroll
    for (int n = 0; n < 8; ++n)
        #pragma unroll
        for (int j = 0; j < 4; ++j) d[n][j] = 0.0f;
    mm3<4, ACT_LD>(d, sb + F_HI, sb + F_LO, sb + WD_HI, sb + WD_LO, a_off, b_off);
    {
        float p0 = 0.0f, p1 = 0.0f;
        #pragma unroll
        for (int n = 0; n < 8; ++n) {
            int c0 = n * 8 + cq;
            float2 bp = *(const float2*)(sm + OFF_BP1 + c0 * 4);
            float2 w2 = *(const float2*)(sm + OFF_WP2 + c0 * 4);
            p0 = fmaf(w2.x, fast_tanh(d[n][0] + bp.x), p0);
            p0 = fmaf(w2.y, fast_tanh(d[n][1] + bp.y), p0);
            p1 = fmaf(w2.x, fast_tanh(d[n][2] + bp.x), p1);
            p1 = fmaf(w2.y, fast_tanh(d[n][3] + bp.y), p1);
        }
        p0 += __shfl_xor_sync(0xFFFFFFFFu, p0, 1);
        p0 += __shfl_xor_sync(0xFFFFFFFFu, p0, 2);
        p1 += __shfl_xor_sync(0xFFFFFFFFu, p1, 1);
        p1 += __shfl_xor_sync(0xFFFFFFFFu, p1, 2);
        if ((lane & 3) == 0) {
            float b2 = ((const float*)(sm + OFF_B2))[0];
            size_t base = (size_t)b * T + t0 + m0;
            out[base + r0]     = b2 + p0;
            out[base + r0 + 8] = b2 + p1;
        }
    }
}

extern "C" void kernel_launch(void* const* d_in, const int* in_sizes, int n_in,
                              void* d_out, int out_size)
{
    const float* x        = (const float*)d_in[0];
    const float* w_causal = (const float*)d_in[1];
    const float* b_causal = (const float*)d_in[2];
    const float* w_dil    = (const float*)d_in[3];
    const float* b_dil    = (const float*)d_in[4];
    const float* w_res    = (const float*)d_in[5];
    const float* b_res    = (const float*)d_in[6];
    const float* w_skip   = (const float*)d_in[7];
    const float* b_skip   = (const float*)d_in[8];
    const float* w_post1  = (const float*)d_in[9];
    const float* b_post1  = (const float*)d_in[10];
    const float* w_post2  = (const float*)d_in[11];
    const float* b_post2  = (const float*)d_in[12];
    float* out = (float*)d_out;

    const int B = 4;
    const int T = out_size / B;   // 65536

    cudaFuncSetAttribute(wavenet_mma,
                         cudaFuncAttributeMaxDynamicSharedMemorySize, SMEM_BYTES);

    dim3 grid(T / 128, B);
    wavenet_mma<<<grid, 256, SMEM_BYTES>>>(
        x, w_causal, b_causal, w_dil, b_dil, w_res, b_res,
        w_skip, b_skip, w_post1, b_post1, w_post2, b_post2, out, T);
}

// round 5
// speedup vs baseline: 2.1065x; 1.2074x over previous
#include <cuda_runtime.h>
#include <cuda_bf16.h>
#include <cstdint>

#define L_LAYERS 20
#define ACT_LD   144       // activation/weight plane row stride (64ch*2B + 16 pad)
#define WC_LD    176       // causal plane row stride (80ch*2B + 16 pad)
#define NTH      384       // 8 compute warps + 4 producer warps

// ---- smem byte offsets ----
#define H_HI   0           // [128][144]
#define H_LO   18432
#define F_HI   36864
#define F_LO   55296
#define WBUF0  73728       // weight planes buf0: WD_HI,WD_LO,WS_HI,WS_LO,WR_HI,WR_LO @ 9216 each
#define WBUF1  129024      // buf1 (also x planes during causal)
#define WB_SZ  55296
#define OFF_BDR  184320    // [2 buf][bd 64 | br 64] f32  (1024 B)
#define OFF_BC   185344
#define OFF_BTOT 185600
#define OFF_BP1  185856
#define OFF_WP2  186112
#define OFF_B2   186368
#define SMEM_BYTES 186384
// causal-phase aliases
#define X_HI   129024      // x planes [128][176] in WBUF1 (consumed before buf1 is staged)
#define X_LO   151552
#define WCA_HI 36864       // w_causal planes [64][176] in F region (F unused until layer0)
#define WCA_LO 48128

__device__ __forceinline__ uint32_t smem_u32(const void* p) {
    uint32_t a;
    asm("{ .reg .u64 t; cvta.to.shared.u64 t, %1; cvt.u32.u64 %0, t; }" : "=r"(a) : "l"(p));
    return a;
}
__device__ __forceinline__ void ldsm4(uint32_t addr, uint32_t r[4]) {
    asm volatile("ldmatrix.sync.aligned.m8n8.x4.shared.b16 {%0,%1,%2,%3}, [%4];"
                 : "=r"(r[0]), "=r"(r[1]), "=r"(r[2]), "=r"(r[3]) : "r"(addr));
}
__device__ __forceinline__ void mma16816(float d[4], const uint32_t a[4],
                                         uint32_t b0, uint32_t b1) {
    asm volatile("mma.sync.aligned.m16n8k16.row.col.f32.bf16.bf16.f32 "
                 "{%0,%1,%2,%3},{%4,%5,%6,%7},{%8,%9},{%0,%1,%2,%3};"
                 : "+f"(d[0]), "+f"(d[1]), "+f"(d[2]), "+f"(d[3])
                 : "r"(a[0]), "r"(a[1]), "r"(a[2]), "r"(a[3]), "r"(b0), "r"(b1));
}
__device__ __forceinline__ float fast_tanh(float x) {
    float e = __expf(2.0f * x);
    return 1.0f - __fdividef(2.0f, e + 1.0f);
}
__device__ __forceinline__ void split_pair(float a, float b, uint32_t& hi, uint32_t& lo) {
    __nv_bfloat16 ha = __float2bfloat16_rn(a), hb = __float2bfloat16_rn(b);
    float ra = a - __bfloat162float(ha), rb = b - __bfloat162float(hb);
    __nv_bfloat16 la = __float2bfloat16_rn(ra), lb = __float2bfloat16_rn(rb);
    hi = (uint32_t)__bfloat16_as_ushort(ha) | ((uint32_t)__bfloat16_as_ushort(hb) << 16);
    lo = (uint32_t)__bfloat16_as_ushort(la) | ((uint32_t)__bfloat16_as_ushort(lb) << 16);
}

// split-precision matmul accumulate with A/B fragment reuse:
// d += Ahi*Bhi + Alo*Bhi + Ahi*Blo
template<int NKC, int LDB>
__device__ __forceinline__ void mm3(float d[8][4],
                                    uint32_t aH, uint32_t aL,
                                    uint32_t bH, uint32_t bL,
                                    uint32_t aoff, uint32_t boff) {
    #pragma unroll
    for (int kc = 0; kc < NKC; ++kc) {
        uint32_t afH[4], afL[4];
        ldsm4(aH + aoff + kc * 32, afH);
        ldsm4(aL + aoff + kc * 32, afL);
        #pragma unroll
        for (int np = 0; np < 4; ++np) {
            uint32_t bf[4];
            ldsm4(bH + boff + kc * 32 + np * (16 * LDB), bf);
            mma16816(d[np*2],   afH, bf[0], bf[1]);
            mma16816(d[np*2+1], afH, bf[2], bf[3]);
            mma16816(d[np*2],   afL, bf[0], bf[1]);
            mma16816(d[np*2+1], afL, bf[2], bf[3]);
            ldsm4(bL + boff + kc * 32 + np * (16 * LDB), bf);
            mma16816(d[np*2],   afH, bf[0], bf[1]);
            mma16816(d[np*2+1], afH, bf[2], bf[3]);
        }
    }
}
// fused: ds += A x Ws ; dr += A x Wr (shared A fragments)
__device__ __forceinline__ void mm3_dual(float ds[8][4], float dr[8][4],
                                         uint32_t aH, uint32_t aL,
                                         uint32_t sH, uint32_t sL,
                                         uint32_t rH, uint32_t rL,
                                         uint32_t aoff, uint32_t boff) {
    #pragma unroll
    for (int kc = 0; kc < 4; ++kc) {
        uint32_t afH[4], afL[4];
        ldsm4(aH + aoff + kc * 32, afH);
        ldsm4(aL + aoff + kc * 32, afL);
        #pragma unroll
        for (int np = 0; np < 4; ++np) {
            uint32_t bf[4];
            uint32_t o = boff + kc * 32 + np * (16 * ACT_LD);
            ldsm4(sH + o, bf);
            mma16816(ds[np*2],   afH, bf[0], bf[1]);
            mma16816(ds[np*2+1], afH, bf[2], bf[3]);
            mma16816(ds[np*2],   afL, bf[0], bf[1]);
            mma16816(ds[np*2+1], afL, bf[2], bf[3]);
            ldsm4(sL + o, bf);
            mma16816(ds[np*2],   afH, bf[0], bf[1]);
            mma16816(ds[np*2+1], afH, bf[2], bf[3]);
            ldsm4(rH + o, bf);
            mma16816(dr[np*2],   afH, bf[0], bf[1]);
            mma16816(dr[np*2+1], afH, bf[2], bf[3]);
            mma16816(dr[np*2],   afL, bf[0], bf[1]);
            mma16816(dr[np*2+1], afL, bf[2], bf[3]);
            ldsm4(rL + o, bf);
            mma16816(dr[np*2],   afH, bf[0], bf[1]);
            mma16816(dr[np*2+1], afH, bf[2], bf[3]);
        }
    }
}

// stage one [64][64] f32 weight into bf16 hi/lo planes ([64][ACT_LD]); NT threads
template<int NT>
__device__ __forceinline__ void stage_w(const float* __restrict__ w, char* sm,
                                        int hiOff, int loOff, int tid) {
    const float4* w4 = (const float4*)w;
    #pragma unroll
    for (int i = tid; i < 1024; i += NT) {
        float4 v = w4[i];
        uint32_t h0, l0, h1, l1;
        split_pair(v.x, v.y, h0, l0);
        split_pair(v.z, v.w, h1, l1);
        int off = (i >> 4) * ACT_LD + (i & 15) * 8;
        *(uint2*)(sm + hiOff + off) = make_uint2(h0, h1);
        *(uint2*)(sm + loOff + off) = make_uint2(l0, l1);
    }
}

__global__ __launch_bounds__(NTH, 1)
void wavenet_ws(const float* __restrict__ x,
                const float* __restrict__ w_causal, const float* __restrict__ b_causal,
                const float* __restrict__ w_dil,    const float* __restrict__ b_dil,
                const float* __restrict__ w_res,    const float* __restrict__ b_res,
                const float* __restrict__ w_skip,   const float* __restrict__ b_skip,
                const float* __restrict__ w_post1,  const float* __restrict__ b_post1,
                const float* __restrict__ w_post2,  const float* __restrict__ b_post2,
                float* __restrict__ out, int T)
{
    extern __shared__ char sm[];
    const uint32_t sb = smem_u32(sm);
    const int tid  = threadIdx.x;
    const int wid  = tid >> 5;
    const int lane = tid & 31;
    const int b    = blockIdx.y;
    const long t0  = (long)blockIdx.x * 128;
    const bool is_compute = (wid < 8);
    const int m0   = wid * 16;                  // valid for compute warps

    const uint32_t a_off  = (uint32_t)(m0 + (lane & 15)) * ACT_LD + ((lane >> 4) << 4);
    const uint32_t b_off  = (uint32_t)((lane & 7) + ((lane >> 4) & 1) * 8) * ACT_LD
                          + (((lane >> 3) & 1) << 4);
    const uint32_t a_offc = (uint32_t)(m0 + (lane & 15)) * WC_LD + ((lane >> 4) << 4);
    const uint32_t b_offc = (uint32_t)((lane & 7) + ((lane >> 4) & 1) * 8) * WC_LD
                          + (((lane >> 3) & 1) << 4);
    const int r0 = (lane >> 2);
    const int cq = (lane & 3) * 2;

    // ---- stage x planes + w_causal planes + bc (all 384 threads) ----
    const float* xg = x + (size_t)b * 80 * (size_t)T + t0;
    for (int i = tid; i < 80 * 128; i += NTH) {
        int ch = i >> 7, t = i & 127;
        float v = xg[(size_t)ch * T + t];
        __nv_bfloat16 hb = __float2bfloat16_rn(v);
        __nv_bfloat16 lb = __float2bfloat16_rn(v - __bfloat162float(hb));
        int off = t * WC_LD + ch * 2;
        *(__nv_bfloat16*)(sm + X_HI + off) = hb;
        *(__nv_bfloat16*)(sm + X_LO + off) = lb;
    }
    for (int i = tid; i < 64 * 80; i += NTH) {
        int o = i / 80, k = i - o * 80;
        float v = w_causal[i];
        __nv_bfloat16 hb = __float2bfloat16_rn(v);
        __nv_bfloat16 lb = __float2bfloat16_rn(v - __bfloat162float(hb));
        int off = o * WC_LD + k * 2;
        *(__nv_bfloat16*)(sm + WCA_HI + off) = hb;
        *(__nv_bfloat16*)(sm + WCA_LO + off) = lb;
    }
    if (tid < 64) ((float*)(sm + OFF_BC))[tid] = b_causal[tid];
    __syncthreads();

    float h[8][4], skip[8][4];
    #pragma unroll
    for (int n = 0; n < 8; ++n)
        #pragma unroll
        for (int j = 0; j < 4; ++j) { h[n][j] = 0.0f; skip[n][j] = 0.0f; }

    if (is_compute) {
        // causal: h = Wc @ x + bc
        mm3<5, WC_LD>(h, sb + X_HI, sb + X_LO, sb + WCA_HI, sb + WCA_LO, a_offc, b_offc);
        int soff = (m0 + r0) * ACT_LD;
        #pragma unroll
        for (int n = 0; n < 8; ++n) {
            float2 bc = *(const float2*)(sm + OFF_BC + (n * 8 + cq) * 4);
            h[n][0] += bc.x; h[n][1] += bc.y; h[n][2] += bc.x; h[n][3] += bc.y;
            int o = soff + (n * 8 + cq) * 2;
            uint32_t hi, lo;
            split_pair(h[n][0], h[n][1], hi, lo);
            *(uint32_t*)(sm + H_HI + o) = hi; *(uint32_t*)(sm + H_LO + o) = lo;
            split_pair(h[n][2], h[n][3], hi, lo);
            *(uint32_t*)(sm + H_HI + o + 8 * ACT_LD) = hi;
            *(uint32_t*)(sm + H_LO + o + 8 * ACT_LD) = lo;
        }
    } else {
        // producers: stage layer-0 weights into buf0
        int p = tid - 256;
        stage_w<128>(w_dil,  sm, WBUF0 + 0,     WBUF0 + 9216,  p);
        stage_w<128>(w_skip, sm, WBUF0 + 18432, WBUF0 + 27648, p);
        stage_w<128>(w_res,  sm, WBUF0 + 36864, WBUF0 + 46080, p);
        if (p < 64)       ((float*)(sm + OFF_BDR))[p]       = b_dil[p];
        else              ((float*)(sm + OFF_BDR))[64 + p - 64 + 0] = 0.0f; // placeholder lane
        if (p >= 64)      ((float*)(sm + OFF_BDR + 256))[p - 64] = b_res[p - 64];
    }
    __syncthreads();

    // ================= layer loop =================
    #pragma unroll 1
    for (int l = 0; l < L_LAYERS; ++l) {
        const uint32_t wb = sb + (uint32_t)((l & 1) ? WBUF1 : WBUF0);
        if (is_compute) {
            // ---- f = tanh(Wd @ h + bd) ----
            float d[8][4];
            #pragma unroll
            for (int n = 0; n < 8; ++n)
                #pragma unroll
                for (int j = 0; j < 4; ++j) d[n][j] = 0.0f;
            mm3<4, ACT_LD>(d, sb + H_HI, sb + H_LO, wb + 0, wb + 9216, a_off, b_off);
            {
                int soff = (m0 + r0) * ACT_LD;
                const char* bdp = sm + OFF_BDR + (l & 1) * 512;
                #pragma unroll
                for (int n = 0; n < 8; ++n) {
                    float2 bd = *(const float2*)(bdp + (n * 8 + cq) * 4);
                    float v0 = fast_tanh(d[n][0] + bd.x), v1 = fast_tanh(d[n][1] + bd.y);
                    float v2 = fast_tanh(d[n][2] + bd.x), v3 = fast_tanh(d[n][3] + bd.y);
                    int o = soff + (n * 8 + cq) * 2;
                    uint32_t hi, lo;
                    split_pair(v0, v1, hi, lo);
                    *(uint32_t*)(sm + F_HI + o) = hi; *(uint32_t*)(sm + F_LO + o) = lo;
                    split_pair(v2, v3, hi, lo);
                    *(uint32_t*)(sm + F_HI + o + 8 * ACT_LD) = hi;
                    *(uint32_t*)(sm + F_LO + o + 8 * ACT_LD) = lo;
                }
            }
            __syncwarp();

            // ---- skip += Ws @ f ; h += Wr @ f + br ----
            #pragma unroll
            for (int n = 0; n < 8; ++n)
                #pragma unroll
                for (int j = 0; j < 4; ++j) d[n][j] = 0.0f;
            mm3_dual(skip, d, sb + F_HI, sb + F_LO,
                     wb + 18432, wb + 27648, wb + 36864, wb + 46080, a_off, b_off);
            {
                int soff = (m0 + r0) * ACT_LD;
                const char* brp = sm + OFF_BDR + (l & 1) * 512 + 256;
                #pragma unroll
                for (int n = 0; n < 8; ++n) {
                    float2 br2 = *(const float2*)(brp + (n * 8 + cq) * 4);
                    h[n][0] += d[n][0] + br2.x; h[n][1] += d[n][1] + br2.y;
                    h[n][2] += d[n][2] + br2.x; h[n][3] += d[n][3] + br2.y;
                    int o = soff + (n * 8 + cq) * 2;
                    uint32_t hi, lo;
                    split_pair(h[n][0], h[n][1], hi, lo);
                    *(uint32_t*)(sm + H_HI + o) = hi; *(uint32_t*)(sm + H_LO + o) = lo;
                    split_pair(h[n][2], h[n][3], hi, lo);
                    *(uint32_t*)(sm + H_HI + o + 8 * ACT_LD) = hi;
                    *(uint32_t*)(sm + H_LO + o + 8 * ACT_LD) = lo;
                }
            }
        } else {
            // ---- producers: stage layer l+1 (or post) into the other buffer ----
            int p = tid - 256;
            int nb = (l + 1) & 1;
            char* wn = sm + (nb ? WBUF1 : WBUF0);
            if (l < L_LAYERS - 1) {
                stage_w<128>(w_dil  + (l + 1) * 4096, wn, 0,     9216,  p);
                stage_w<128>(w_skip + (l + 1) * 4096, wn, 18432, 27648, p);
                stage_w<128>(w_res  + (l + 1) * 4096, wn, 36864, 46080, p);
                if (p < 64)  ((float*)(sm + OFF_BDR + nb * 512))[p]        = b_dil[(l + 1) * 64 + p];
                else         ((float*)(sm + OFF_BDR + nb * 512 + 256))[p - 64] = b_res[(l + 1) * 64 + p - 64];
            } else {
                stage_w<128>(w_post1, wn, 0, 9216, p);
                if (p < 64) {
                    float s = 0.0f;
                    #pragma unroll
                    for (int ll = 0; ll < L_LAYERS; ++ll) s += b_skip[ll * 64 + p];
                    ((float*)(sm + OFF_BTOT))[p] = s;
                    ((float*)(sm + OFF_BP1))[p]  = b_post1[p];
                    ((float*)(sm + OFF_WP2))[p]  = w_post2[p];
                }
                if (p == 64) ((float*)(sm + OFF_B2))[0] = b_post2[0];
            }
        }
        __syncthreads();
    }

    // ================= post =================
    if (is_compute) {
        // s = tanh(skip + btot) -> F planes
        {
            int soff = (m0 + r0) * ACT_LD;
            #pragma unroll
            for (int n = 0; n < 8; ++n) {
                float2 bt = *(const float2*)(sm + OFF_BTOT + (n * 8 + cq) * 4);
                float v0 = fast_tanh(skip[n][0] + bt.x), v1 = fast_tanh(skip[n][1] + bt.y);
                float v2 = fast_tanh(skip[n][2] + bt.x), v3 = fast_tanh(skip[n][3] + bt.y);
                int o = soff + (n * 8 + cq) * 2;
                uint32_t hi, lo;
                split_pair(v0, v1, hi, lo);
                *(uint32_t*)(sm + F_HI + o) = hi; *(uint32_t*)(sm + F_LO + o) = lo;
                split_pair(v2, v3, hi, lo);
                *(uint32_t*)(sm + F_HI + o + 8 * ACT_LD) = hi;
                *(uint32_t*)(sm + F_LO + o + 8 * ACT_LD) = lo;
            }
        }
        __syncwarp();

        // s2 = tanh(W1 @ s + bp1); out = b2 + wp2 . s2   (W1 staged in buf[0] WD slot)
        const uint32_t wb = sb + (uint32_t)((L_LAYERS & 1) ? WBUF1 : WBUF0);
        float d[8][4];
        #pragma unroll
        for (int n = 0; n < 8; ++n)
            #pragma unroll
            for (int j = 0; j < 4; ++j) d[n][j] = 0.0f;
        mm3<4, ACT_LD>(d, sb + F_HI, sb + F_LO, wb + 0, wb + 9216, a_off, b_off);
        {
            float p0 = 0.0f, p1 = 0.0f;
            #pragma unroll
            for (int n = 0; n < 8; ++n) {
                int c0 = n * 8 + cq;
                float2 bp = *(const float2*)(sm + OFF_BP1 + c0 * 4);
                float2 w2 = *(const float2*)(sm + OFF_WP2 + c0 * 4);
                p0 = fmaf(w2.x, fast_tanh(d[n][0] + bp.x), p0);
                p0 = fmaf(w2.y, fast_tanh(d[n][1] + bp.y), p0);
                p1 = fmaf(w2.x, fast_tanh(d[n][2] + bp.x), p1);
                p1 = fmaf(w2.y, fast_tanh(d[n][3] + bp.y), p1);
            }
            p0 += __shfl_xor_sync(0xFFFFFFFFu, p0, 1);
            p0 += __shfl_xor_sync(0xFFFFFFFFu, p0, 2);
            p1 += __shfl_xor_sync(0xFFFFFFFFu, p1, 1);
            p1 += __shfl_xor_sync(0xFFFFFFFFu, p1, 2);
            if ((lane & 3) == 0) {
                float b2 = ((const float*)(sm + OFF_B2))[0];
                size_t base = (size_t)b * T + t0 + m0;
                out[base + r0]     = b2 + p0;
                out[base + r0 + 8] = b2 + p1;
            }
        }
    }
}

extern "C" void kernel_launch(void* const* d_in, const int* in_sizes, int n_in,
                              void* d_out, int out_size)
{
    const float* x        = (const float*)d_in[0];
    const float* w_causal = (const float*)d_in[1];
    const float* b_causal = (const float*)d_in[2];
    const float* w_dil    = (const float*)d_in[3];
    const float* b_dil    = (const float*)d_in[4];
    const float* w_res    = (const float*)d_in[5];
    const float* b_res    = (const float*)d_in[6];
    const float* w_skip   = (const float*)d_in[7];
    const float* b_skip   = (const float*)d_in[8];
    const float* w_post1  = (const float*)d_in[9];
    const float* b_post1  = (const float*)d_in[10];
    const float* w_post2  = (const float*)d_in[11];
    const float* b_post2  = (const float*)d_in[12];
    float* out = (float*)d_out;

    const int B = 4;
    const int T = out_size / B;   // 65536

    cudaFuncSetAttribute(wavenet_ws,
                         cudaFuncAttributeMaxDynamicSharedMemorySize, SMEM_BYTES);

    dim3 grid(T / 128, B);
    wavenet_ws<<<grid, NTH, SMEM_BYTES>>>(
        x, w_causal, b_causal, w_dil, b_dil, w_res, b_res,
        w_skip, b_skip, w_post1, b_post1, w_post2, b_post2, out, T);
}

// round 6
// speedup vs baseline: 3.0653x; 1.4551x over previous
#include <cuda_runtime.h>
#include <cuda_bf16.h>
#include <cstdint>

#define L_LAYERS 20
#define ACT_LD   144       // weight plane row stride (64*2B + 16 pad)
#define WC_LD    176       // causal plane row stride (80*2B + 16 pad)
#define NTH      384       // 8 compute warps + 4 producer warps

// ---- smem layout (bytes) ----
// WBUF: 6 planes (WD_HI,WD_LO,WS_HI,WS_LO,WR_HI,WR_LO) @ 9216 each = 55296
#define WBUF0    0
#define WBUF1    55296
#define SCRATCH  110592    // WCA planes during causal
#define WCA_HI   110592
#define WCA_LO   121856
#define OFF_BDR  133120    // [2 buf][bd 64 | br 64] f32
#define OFF_BC   134144
#define OFF_BTOT 134400
#define OFF_BP1  134656
#define OFF_WP2  134912
#define OFF_B2   135168
#define SMEM_BYTES 135296
// causal x planes alias WBUF1 (consumed before layer-1 staging)
#define X_HI     55296
#define X_LO     77824

__device__ __forceinline__ uint32_t smem_u32(const void* p) {
    uint32_t a;
    asm("{ .reg .u64 t; cvta.to.shared.u64 t, %1; cvt.u32.u64 %0, t; }" : "=r"(a) : "l"(p));
    return a;
}
__device__ __forceinline__ void ldsm4(uint32_t addr, uint32_t r[4]) {
    asm volatile("ldmatrix.sync.aligned.m8n8.x4.shared.b16 {%0,%1,%2,%3}, [%4];"
                 : "=r"(r[0]), "=r"(r[1]), "=r"(r[2]), "=r"(r[3]) : "r"(addr));
}
__device__ __forceinline__ void mma16816(float d[4], const uint32_t a[4],
                                         uint32_t b0, uint32_t b1) {
    asm volatile("mma.sync.aligned.m16n8k16.row.col.f32.bf16.bf16.f32 "
                 "{%0,%1,%2,%3},{%4,%5,%6,%7},{%8,%9},{%0,%1,%2,%3};"
                 : "+f"(d[0]), "+f"(d[1]), "+f"(d[2]), "+f"(d[3])
                 : "r"(a[0]), "r"(a[1]), "r"(a[2]), "r"(a[3]), "r"(b0), "r"(b1));
}
__device__ __forceinline__ float fast_tanh(float x) {
    float e = __expf(2.0f * x);
    return 1.0f - __fdividef(2.0f, e + 1.0f);
}
// pack fp32 pair -> bf16x2 hi + bf16x2 lo (lo = residual)
__device__ __forceinline__ void pack_pair(float x, float y, uint32_t& hi, uint32_t& lo) {
    asm("cvt.rn.bf16x2.f32 %0, %1, %2;" : "=r"(hi) : "f"(y), "f"(x)); // hi16=y, lo16=x
    float xh = __uint_as_float(hi << 16);
    float yh = __uint_as_float(hi & 0xffff0000u);
    float xl = x - xh, yl = y - yh;
    asm("cvt.rn.bf16x2.f32 %0, %1, %2;" : "=r"(lo) : "f"(yl), "f"(xl));
}
__device__ __forceinline__ void split_pair(float a, float b, uint32_t& hi, uint32_t& lo) {
    pack_pair(a, b, hi, lo);
}

// d += A x B with A fragments in registers (hi+lo passes), B planes in smem
__device__ __forceinline__ void mm3_reg(float d[8][4],
                                        const uint32_t aH[4][4], const uint32_t aL[4][4],
                                        uint32_t bH, uint32_t bL, uint32_t boff) {
    #pragma unroll
    for (int kc = 0; kc < 4; ++kc) {
        #pragma unroll
        for (int np = 0; np < 4; ++np) {
            uint32_t bf[4];
            uint32_t o = boff + kc * 32 + np * (16 * ACT_LD);
            ldsm4(bH + o, bf);
            mma16816(d[np*2],   aH[kc], bf[0], bf[1]);
            mma16816(d[np*2+1], aH[kc], bf[2], bf[3]);
            mma16816(d[np*2],   aL[kc], bf[0], bf[1]);
            mma16816(d[np*2+1], aL[kc], bf[2], bf[3]);
            ldsm4(bL + o, bf);
            mma16816(d[np*2],   aH[kc], bf[0], bf[1]);
            mma16816(d[np*2+1], aH[kc], bf[2], bf[3]);
        }
    }
}
// ds += A x Ws ; dr += A x Wr (A fragments shared, in registers)
__device__ __forceinline__ void mm3_dual_reg(float ds[8][4], float dr[8][4],
                                             const uint32_t aH[4][4], const uint32_t aL[4][4],
                                             uint32_t sH, uint32_t sL,
                                             uint32_t rH, uint32_t rL, uint32_t boff) {
    #pragma unroll
    for (int kc = 0; kc < 4; ++kc) {
        #pragma unroll
        for (int np = 0; np < 4; ++np) {
            uint32_t bf[4];
            uint32_t o = boff + kc * 32 + np * (16 * ACT_LD);
            ldsm4(sH + o, bf);
            mma16816(ds[np*2],   aH[kc], bf[0], bf[1]);
            mma16816(ds[np*2+1], aH[kc], bf[2], bf[3]);
            mma16816(ds[np*2],   aL[kc], bf[0], bf[1]);
            mma16816(ds[np*2+1], aL[kc], bf[2], bf[3]);
            ldsm4(sL + o, bf);
            mma16816(ds[np*2],   aH[kc], bf[0], bf[1]);
            mma16816(ds[np*2+1], aH[kc], bf[2], bf[3]);
            ldsm4(rH + o, bf);
            mma16816(dr[np*2],   aH[kc], bf[0], bf[1]);
            mma16816(dr[np*2+1], aH[kc], bf[2], bf[3]);
            mma16816(dr[np*2],   aL[kc], bf[0], bf[1]);
            mma16816(dr[np*2+1], aL[kc], bf[2], bf[3]);
            ldsm4(rL + o, bf);
            mma16816(dr[np*2],   aH[kc], bf[0], bf[1]);
            mma16816(dr[np*2+1], aH[kc], bf[2], bf[3]);
        }
    }
}
// causal: d += A x B, A planes in smem (K = 80 -> 5 k-chunks)
__device__ __forceinline__ void mm3_smem(float d[8][4],
                                         uint32_t aH, uint32_t aL,
                                         uint32_t bH, uint32_t bL,
                                         uint32_t aoff, uint32_t boff) {
    #pragma unroll
    for (int kc = 0; kc < 5; ++kc) {
        uint32_t afH[4], afL[4];
        ldsm4(aH + aoff + kc * 32, afH);
        ldsm4(aL + aoff + kc * 32, afL);
        #pragma unroll
        for (int np = 0; np < 4; ++np) {
            uint32_t bf[4];
            uint32_t o = boff + kc * 32 + np * (16 * WC_LD);
            ldsm4(bH + o, bf);
            mma16816(d[np*2],   afH, bf[0], bf[1]);
            mma16816(d[np*2+1], afH, bf[2], bf[3]);
            mma16816(d[np*2],   afL, bf[0], bf[1]);
            mma16816(d[np*2+1], afL, bf[2], bf[3]);
            ldsm4(bL + o, bf);
            mma16816(d[np*2],   afH, bf[0], bf[1]);
            mma16816(d[np*2+1], afH, bf[2], bf[3]);
        }
    }
}

// stage one [64][64] f32 weight into bf16 hi/lo planes ([64][ACT_LD]); 128 threads
__device__ __forceinline__ void stage_w(const float* __restrict__ w, char* sm,
                                        int hiOff, int loOff, int tid) {
    const float4* w4 = (const float4*)w;
    #pragma unroll
    for (int i = tid; i < 1024; i += 128) {
        float4 v = w4[i];
        uint32_t h0, l0, h1, l1;
        split_pair(v.x, v.y, h0, l0);
        split_pair(v.z, v.w, h1, l1);
        int off = (i >> 4) * ACT_LD + (i & 15) * 8;
        *(uint2*)(sm + hiOff + off) = make_uint2(h0, h1);
        *(uint2*)(sm + loOff + off) = make_uint2(l0, l1);
    }
}

__global__ __launch_bounds__(NTH, 1)
void wavenet_rr(const float* __restrict__ x,
                const float* __restrict__ w_causal, const float* __restrict__ b_causal,
                const float* __restrict__ w_dil,    const float* __restrict__ b_dil,
                const float* __restrict__ w_res,    const float* __restrict__ b_res,
                const float* __restrict__ w_skip,   const float* __restrict__ b_skip,
                const float* __restrict__ w_post1,  const float* __restrict__ b_post1,
                const float* __restrict__ w_post2,  const float* __restrict__ b_post2,
                float* __restrict__ out, int T)
{
    extern __shared__ char sm[];
    const uint32_t sb = smem_u32(sm);
    const int tid  = threadIdx.x;
    const int wid  = tid >> 5;
    const int lane = tid & 31;
    const int b    = blockIdx.y;
    const long t0  = (long)blockIdx.x * 128;
    const bool is_compute = (wid < 8);
    const int m0   = wid * 16;

    const uint32_t b_off  = (uint32_t)((lane & 7) + ((lane >> 4) & 1) * 8) * ACT_LD
                          + (((lane >> 3) & 1) << 4);
    const uint32_t a_offc = (uint32_t)(m0 + (lane & 15)) * WC_LD + ((lane >> 4) << 4);
    const uint32_t b_offc = (uint32_t)((lane & 7) + ((lane >> 4) & 1) * 8) * WC_LD
                          + (((lane >> 3) & 1) << 4);
    const int r0 = (lane >> 2);
    const int cq = (lane & 3) * 2;

    // ---- stage x planes (into WBUF1 alias) + w_causal planes (scratch) + bc ----
    const float* xg = x + (size_t)b * 80 * (size_t)T + t0;
    for (int i = tid; i < 80 * 128; i += NTH) {
        int ch = i >> 7, t = i & 127;
        float v = xg[(size_t)ch * T + t];
        __nv_bfloat16 hb = __float2bfloat16_rn(v);
        __nv_bfloat16 lb = __float2bfloat16_rn(v - __bfloat162float(hb));
        int off = t * WC_LD + ch * 2;
        *(__nv_bfloat16*)(sm + X_HI + off) = hb;
        *(__nv_bfloat16*)(sm + X_LO + off) = lb;
    }
    for (int i = tid; i < 64 * 80; i += NTH) {
        int o = i / 80, k = i - o * 80;
        float v = w_causal[i];
        __nv_bfloat16 hb = __float2bfloat16_rn(v);
        __nv_bfloat16 lb = __float2bfloat16_rn(v - __bfloat162float(hb));
        int off = o * WC_LD + k * 2;
        *(__nv_bfloat16*)(sm + WCA_HI + off) = hb;
        *(__nv_bfloat16*)(sm + WCA_LO + off) = lb;
    }
    if (tid < 64) ((float*)(sm + OFF_BC))[tid] = b_causal[tid];
    __syncthreads();

    float h[8][4], skip[8][4];
    uint32_t ahH[4][4], ahL[4][4];   // h A-fragments (persist across layers)
    #pragma unroll
    for (int n = 0; n < 8; ++n)
        #pragma unroll
        for (int j = 0; j < 4; ++j) { h[n][j] = 0.0f; skip[n][j] = 0.0f; }

    if (is_compute) {
        // causal: h = Wc @ x + bc; build h fragments
        mm3_smem(h, sb + X_HI, sb + X_LO, sb + WCA_HI, sb + WCA_LO, a_offc, b_offc);
        #pragma unroll
        for (int n = 0; n < 8; ++n) {
            float2 bc = *(const float2*)(sm + OFF_BC + (n * 8 + cq) * 4);
            h[n][0] += bc.x; h[n][1] += bc.y; h[n][2] += bc.x; h[n][3] += bc.y;
            int kc = n >> 1, o = (n & 1) * 2;
            pack_pair(h[n][0], h[n][1], ahH[kc][o],   ahL[kc][o]);
            pack_pair(h[n][2], h[n][3], ahH[kc][o+1], ahL[kc][o+1]);
        }
    } else {
        // producers: stage layer-0 weights into WBUF0
        int p = tid - 256;
        stage_w(w_dil,  sm, WBUF0 + 0,     WBUF0 + 9216,  p);
        stage_w(w_skip, sm, WBUF0 + 18432, WBUF0 + 27648, p);
        stage_w(w_res,  sm, WBUF0 + 36864, WBUF0 + 46080, p);
        if (p < 64)      ((float*)(sm + OFF_BDR))[p]             = b_dil[p];
        else             ((float*)(sm + OFF_BDR + 256))[p - 64]  = b_res[p - 64];
    }
    __syncthreads();

    // ================= layer loop =================
    #pragma unroll 1
    for (int l = 0; l < L_LAYERS; ++l) {
        const uint32_t wb = sb + (uint32_t)((l & 1) ? WBUF1 : WBUF0);
        if (is_compute) {
            // ---- f = tanh(Wd @ h + bd) -> A fragments ----
            float d[8][4];
            #pragma unroll
            for (int n = 0; n < 8; ++n)
                #pragma unroll
                for (int j = 0; j < 4; ++j) d[n][j] = 0.0f;
            mm3_reg(d, ahH, ahL, wb + 0, wb + 9216, b_off);

            uint32_t afH[4][4], afL[4][4];
            {
                const char* bdp = sm + OFF_BDR + (l & 1) * 512;
                #pragma unroll
                for (int n = 0; n < 8; ++n) {
                    float2 bd = *(const float2*)(bdp + (n * 8 + cq) * 4);
                    float v0 = fast_tanh(d[n][0] + bd.x), v1 = fast_tanh(d[n][1] + bd.y);
                    float v2 = fast_tanh(d[n][2] + bd.x), v3 = fast_tanh(d[n][3] + bd.y);
                    int kc = n >> 1, o = (n & 1) * 2;
                    pack_pair(v0, v1, afH[kc][o],   afL[kc][o]);
                    pack_pair(v2, v3, afH[kc][o+1], afL[kc][o+1]);
                }
            }

            // ---- skip += Ws @ f ; h += Wr @ f + br -> new h fragments ----
            #pragma unroll
            for (int n = 0; n < 8; ++n)
                #pragma unroll
                for (int j = 0; j < 4; ++j) d[n][j] = 0.0f;
            mm3_dual_reg(skip, d, afH, afL,
                         wb + 18432, wb + 27648, wb + 36864, wb + 46080, b_off);
            {
                const char* brp = sm + OFF_BDR + (l & 1) * 512 + 256;
                #pragma unroll
                for (int n = 0; n < 8; ++n) {
                    float2 br2 = *(const float2*)(brp + (n * 8 + cq) * 4);
                    h[n][0] += d[n][0] + br2.x; h[n][1] += d[n][1] + br2.y;
                    h[n][2] += d[n][2] + br2.x; h[n][3] += d[n][3] + br2.y;
                    int kc = n >> 1, o = (n & 1) * 2;
                    pack_pair(h[n][0], h[n][1], ahH[kc][o],   ahL[kc][o]);
                    pack_pair(h[n][2], h[n][3], ahH[kc][o+1], ahL[kc][o+1]);
                }
            }
        } else {
            // ---- producers: stage layer l+1 (or post) into the other buffer ----
            int p = tid - 256;
            int nb = (l + 1) & 1;
            char* wn = sm + (nb ? WBUF1 : WBUF0);
            if (l < L_LAYERS - 1) {
                stage_w(w_dil  + (l + 1) * 4096, wn, 0,     9216,  p);
                stage_w(w_skip + (l + 1) * 4096, wn, 18432, 27648, p);
                stage_w(w_res  + (l + 1) * 4096, wn, 36864, 46080, p);
                if (p < 64)  ((float*)(sm + OFF_BDR + nb * 512))[p]           = b_dil[(l + 1) * 64 + p];
                else         ((float*)(sm + OFF_BDR + nb * 512 + 256))[p - 64] = b_res[(l + 1) * 64 + p - 64];
            } else {
                stage_w(w_post1, wn, 0, 9216, p);
                if (p < 64) {
                    float s = 0.0f;
                    #pragma unroll
                    for (int ll = 0; ll < L_LAYERS; ++ll) s += b_skip[ll * 64 + p];
                    ((float*)(sm + OFF_BTOT))[p] = s;
                    ((float*)(sm + OFF_BP1))[p]  = b_post1[p];
                    ((float*)(sm + OFF_WP2))[p]  = w_post2[p];
                }
                if (p == 64) ((float*)(sm + OFF_B2))[0] = b_post2[0];
            }
        }
        __syncthreads();
    }

    // ================= post =================
    if (is_compute) {
        // s = tanh(skip + btot) -> fragments
        uint32_t afH[4][4], afL[4][4];
        #pragma unroll
        for (int n = 0; n < 8; ++n) {
            float2 bt = *(const float2*)(sm + OFF_BTOT + (n * 8 + cq) * 4);
            float v0 = fast_tanh(skip[n][0] + bt.x), v1 = fast_tanh(skip[n][1] + bt.y);
            float v2 = fast_tanh(skip[n][2] + bt.x), v3 = fast_tanh(skip[n][3] + bt.y);
            int kc = n >> 1, o = (n & 1) * 2;
            pack_pair(v0, v1, afH[kc][o],   afL[kc][o]);
            pack_pair(v2, v3, afH[kc][o+1], afL[kc][o+1]);
        }

        // s2 = tanh(W1 @ s + bp1); out = b2 + wp2 . s2   (W1 in buf0 dil slot)
        const uint32_t wb = sb + (uint32_t)((L_LAYERS & 1) ? WBUF1 : WBUF0);
        float d[8][4];
        #pragma unroll
        for (int n = 0; n < 8; ++n)
            #pragma unroll
            for (int j = 0; j < 4; ++j) d[n][j] = 0.0f;
        mm3_reg(d, afH, afL, wb + 0, wb + 9216, b_off);
        {
            float p0 = 0.0f, p1 = 0.0f;
            #pragma unroll
            for (int n = 0; n < 8; ++n) {
                int c0 = n * 8 + cq;
                float2 bp = *(const float2*)(sm + OFF_BP1 + c0 * 4);
                float2 w2 = *(const float2*)(sm + OFF_WP2 + c0 * 4);
                p0 = fmaf(w2.x, fast_tanh(d[n][0] + bp.x), p0);
                p0 = fmaf(w2.y, fast_tanh(d[n][1] + bp.y), p0);
                p1 = fmaf(w2.x, fast_tanh(d[n][2] + bp.x), p1);
                p1 = fmaf(w2.y, fast_tanh(d[n][3] + bp.y), p1);
            }
            p0 += __shfl_xor_sync(0xFFFFFFFFu, p0, 1);
            p0 += __shfl_xor_sync(0xFFFFFFFFu, p0, 2);
            p1 += __shfl_xor_sync(0xFFFFFFFFu, p1, 1);
            p1 += __shfl_xor_sync(0xFFFFFFFFu, p1, 2);
            if ((lane & 3) == 0) {
                float b2 = ((const float*)(sm + OFF_B2))[0];
                size_t base = (size_t)b * T + t0 + m0;
                out[base + r0]     = b2 + p0;
                out[base + r0 + 8] = b2 + p1;
            }
        }
    }
}

extern "C" void kernel_launch(void* const* d_in, const int* in_sizes, int n_in,
                              void* d_out, int out_size)
{
    const float* x        = (const float*)d_in[0];
    const float* w_causal = (const float*)d_in[1];
    const float* b_causal = (const float*)d_in[2];
    const float* w_dil    = (const float*)d_in[3];
    const float* b_dil    = (const float*)d_in[4];
    const float* w_res    = (const float*)d_in[5];
    const float* b_res    = (const float*)d_in[6];
    const float* w_skip   = (const float*)d_in[7];
    const float* b_skip   = (const float*)d_in[8];
    const float* w_post1  = (const float*)d_in[9];
    const float* b_post1  = (const float*)d_in[10];
    const float* w_post2  = (const float*)d_in[11];
    const float* b_post2  = (const float*)d_in[12];
    float* out = (float*)d_out;

    const int B = 4;
    const int T = out_size / B;   // 65536

    cudaFuncSetAttribute(wavenet_rr,
                         cudaFuncAttributeMaxDynamicSharedMemorySize, SMEM_BYTES);

    dim3 grid(T / 128, B);
    wavenet_rr<<<grid, NTH, SMEM_BYTES>>>(
        x, w_causal, b_causal, w_dil, b_dil, w_res, b_res,
        w_skip, b_skip, w_post1, b_post1, w_post2, b_post2, out, T);
}